// round 1
// baseline (speedup 1.0000x reference)
#include <cuda_runtime.h>
#include <math.h>

#define Bsz 4
#define Lsz 256
#define Hsz 768
#define NL  13

// Scratch for projections (allocation-free: __device__ globals)
__device__ float g_xs[Bsz * Lsz * Hsz];   // xs_proj + b1
__device__ float g_xe[Bsz * Lsz * Hsz];   // xe_proj

// ---------------------------------------------------------------------------
// Kernel 1: fused projection GEMM.
//   Treat as one GEMM: A = hidden (M=1024 x K=768), Bmat = W1 half (768 x 768),
//   global N = 1536 (cols 0..767 -> xs half, 768..1535 -> xe half).
//   64x64 block tile, BK=16, 256 threads, 4x4 per thread.
// ---------------------------------------------------------------------------
#define BM 64
#define BN 64
#define BK 16
#define SPAD 4            // smem row stride = 68 floats (keeps float4 alignment)

__global__ __launch_bounds__(256) void proj_kernel(
    const float* __restrict__ X, const float* __restrict__ W1,
    const float* __restrict__ b1)
{
    __shared__ float As[BK][BM + SPAD];
    __shared__ float Bs[BK][BN + SPAD];

    const int m0  = blockIdx.y * BM;
    const int n0g = blockIdx.x * BN;
    const int half = (n0g >= Hsz) ? 1 : 0;
    const int n0  = n0g - half * Hsz;
    const float* Bbase = W1 + (size_t)half * Hsz * Hsz;  // (768 x 768) row-major
    float* Out = half ? g_xe : g_xs;

    const int tid = threadIdx.x;
    const int tx = tid & 15;
    const int ty = tid >> 4;

    float acc[4][4];
#pragma unroll
    for (int q = 0; q < 4; q++)
#pragma unroll
        for (int p = 0; p < 4; p++) acc[q][p] = 0.f;

    // A-load mapping: each thread loads one float4 of the 64x16 A tile
    const int a_row = tid >> 2;           // 0..63
    const int a_kv  = (tid & 3) * 4;      // 0,4,8,12
    // B-load mapping: each thread loads one float4 of the 16x64 B tile
    const int b_kk = tid >> 4;            // 0..15
    const int b_nv = (tid & 15) * 4;      // 0..60

    for (int k0 = 0; k0 < Hsz; k0 += BK) {
        float4 a = *(const float4*)(X + (size_t)(m0 + a_row) * Hsz + k0 + a_kv);
        As[a_kv + 0][a_row] = a.x;
        As[a_kv + 1][a_row] = a.y;
        As[a_kv + 2][a_row] = a.z;
        As[a_kv + 3][a_row] = a.w;
        float4 bv = *(const float4*)(Bbase + (size_t)(k0 + b_kk) * Hsz + n0 + b_nv);
        *(float4*)&Bs[b_kk][b_nv] = bv;
        __syncthreads();

#pragma unroll
        for (int kk = 0; kk < BK; kk++) {
            float4 av = *(const float4*)&As[kk][ty * 4];
            float4 bw = *(const float4*)&Bs[kk][tx * 4];
            float ar[4] = {av.x, av.y, av.z, av.w};
            float br[4] = {bw.x, bw.y, bw.z, bw.w};
#pragma unroll
            for (int q = 0; q < 4; q++)
#pragma unroll
                for (int p = 0; p < 4; p++)
                    acc[q][p] = fmaf(ar[q], br[p], acc[q][p]);
        }
        __syncthreads();
    }

#pragma unroll
    for (int q = 0; q < 4; q++) {
        const int row = m0 + ty * 4 + q;
#pragma unroll
        for (int p = 0; p < 4; p++) {
            const int col = n0 + tx * 4 + p;
            float v = acc[q][p];
            if (!half) v += b1[col];         // fold b1 into xs half
            Out[(size_t)row * Hsz + col] = v;
        }
    }
}

// ---------------------------------------------------------------------------
// Kernel 2: fused span scorer.
//   Each 256-thread block handles one batch b and a 16x16 (i,j) tile.
//   k is chunked (CK=128); xs/xe staged k-transposed in smem (stride 17,
//   conflict-free), W2 chunk padded to 16 cols for float4 broadcast loads.
//   Per (pair,k): h = xs+xe, exact-erf GELU, 13 FMAs into registers.
// ---------------------------------------------------------------------------
#define TI 16
#define TJ 16
#define CK 128

__global__ __launch_bounds__(256) void span_kernel(
    const float* __restrict__ W2, const float* __restrict__ b2,
    float* __restrict__ out)
{
    __shared__ float W2c[CK][16];
    __shared__ float xss[CK][TI + 1];
    __shared__ float xes[CK][TJ + 1];

    const int b  = blockIdx.z;
    const int i0 = blockIdx.y * TI;
    const int j0 = blockIdx.x * TJ;
    const int tid = threadIdx.x;
    const int il = tid >> 4;   // 0..15
    const int jl = tid & 15;   // 0..15

    const float* xsrow = g_xs + (size_t)(b * Lsz + i0) * Hsz;
    const float* xerow = g_xe + (size_t)(b * Lsz + j0) * Hsz;

    float acc[NL];
#pragma unroll
    for (int n = 0; n < NL; n++) acc[n] = 0.f;

    for (int k0 = 0; k0 < Hsz; k0 += CK) {
        __syncthreads();
        // Stage W2 chunk (pad cols 13..15 with zero)
#pragma unroll
        for (int e = tid; e < CK * 16; e += 256) {
            int kk = e >> 4, n = e & 15;
            W2c[kk][n] = (n < NL) ? W2[(size_t)(k0 + kk) * NL + n] : 0.f;
        }
        // Stage xs/xe chunk, transposed to [kk][row]
#pragma unroll
        for (int e = tid; e < TI * CK; e += 256) {
            int r = e >> 7, kk = e & 127;
            float vs = xsrow[(size_t)r * Hsz + k0 + kk];
            float ve = xerow[(size_t)r * Hsz + k0 + kk];
            xss[kk][r] = vs;
            xes[kk][r] = ve;
        }
        __syncthreads();

#pragma unroll 8
        for (int kk = 0; kk < CK; kk++) {
            float h = xss[kk][il] + xes[kk][jl];
            // exact GELU: 0.5*h*(1+erf(h/sqrt(2))) = t + t*erf(...), t = 0.5h
            float t = 0.5f * h;
            float g = fmaf(t, erff(h * 0.70710678118654752440f), t);
            float4 w0 = *(const float4*)&W2c[kk][0];
            float4 w1 = *(const float4*)&W2c[kk][4];
            float4 w2 = *(const float4*)&W2c[kk][8];
            float4 w3 = *(const float4*)&W2c[kk][12];
            acc[0]  = fmaf(g, w0.x, acc[0]);
            acc[1]  = fmaf(g, w0.y, acc[1]);
            acc[2]  = fmaf(g, w0.z, acc[2]);
            acc[3]  = fmaf(g, w0.w, acc[3]);
            acc[4]  = fmaf(g, w1.x, acc[4]);
            acc[5]  = fmaf(g, w1.y, acc[5]);
            acc[6]  = fmaf(g, w1.z, acc[6]);
            acc[7]  = fmaf(g, w1.w, acc[7]);
            acc[8]  = fmaf(g, w2.x, acc[8]);
            acc[9]  = fmaf(g, w2.y, acc[9]);
            acc[10] = fmaf(g, w2.z, acc[10]);
            acc[11] = fmaf(g, w2.w, acc[11]);
            acc[12] = fmaf(g, w3.x, acc[12]);
        }
    }

    float* op = out + ((size_t)(b * Lsz + i0 + il) * Lsz + (j0 + jl)) * NL;
#pragma unroll
    for (int n = 0; n < NL; n++) op[n] = acc[n] + b2[n];
}

// ---------------------------------------------------------------------------
extern "C" void kernel_launch(void* const* d_in, const int* in_sizes, int n_in,
                              void* d_out, int out_size)
{
    const float* X  = (const float*)d_in[0];   // hidden_states (4,256,768)
    const float* W1 = (const float*)d_in[1];   // (1536,768)
    const float* b1 = (const float*)d_in[2];   // (768)
    const float* W2 = (const float*)d_in[3];   // (768,13)
    const float* b2 = (const float*)d_in[4];   // (13)
    float* out = (float*)d_out;                // (4,256,256,13)

    dim3 g1((2 * Hsz) / BN, (Bsz * Lsz) / BM);   // 24 x 16 = 384 blocks
    proj_kernel<<<g1, 256>>>(X, W1, b1);

    dim3 g2(Lsz / TJ, Lsz / TI, Bsz);            // 16 x 16 x 4 = 1024 blocks
    span_kernel<<<g2, 256>>>(W2, b2, out);
}

// round 3
// speedup vs baseline: 1.2094x; 1.2094x over previous
#include <cuda_runtime.h>
#include <math.h>

#define Bsz 4
#define Lsz 256
#define Hsz 768
#define NL  13

typedef unsigned long long u64;

// ---------------------------------------------------------------------------
// f32x2 packed helpers (Blackwell sm_103a: 2x fp32 throughput per issue slot)
// ---------------------------------------------------------------------------
__device__ __forceinline__ u64 pack2(float lo, float hi) {
    u64 r; asm("mov.b64 %0,{%1,%2};" : "=l"(r) : "f"(lo), "f"(hi)); return r;
}
__device__ __forceinline__ u64 bcast2(float x) { return pack2(x, x); }
__device__ __forceinline__ void unpack2(u64 v, float& lo, float& hi) {
    asm("mov.b64 {%0,%1},%2;" : "=f"(lo), "=f"(hi) : "l"(v));
}
__device__ __forceinline__ u64 fadd2_(u64 a, u64 b) {
    u64 d; asm("add.rn.f32x2 %0,%1,%2;" : "=l"(d) : "l"(a), "l"(b)); return d;
}
__device__ __forceinline__ u64 fmul2_(u64 a, u64 b) {
    u64 d; asm("mul.rn.f32x2 %0,%1,%2;" : "=l"(d) : "l"(a), "l"(b)); return d;
}
__device__ __forceinline__ u64 ffma2_(u64 a, u64 b, u64 c) {
    u64 d; asm("fma.rn.f32x2 %0,%1,%2,%3;" : "=l"(d) : "l"(a), "l"(b), "l"(c)); return d;
}
// no min.f32x2 in PTX: clamp via 2x scalar FMNMX (alu pipe, not fma) + repack
__device__ __forceinline__ u64 fmin2s_(u64 a, float b) {
    float lo, hi; unpack2(a, lo, hi);
    return pack2(fminf(lo, b), fminf(hi, b));
}
__device__ __forceinline__ u64 habs2_(u64 a) { return a & 0x7fffffff7fffffffULL; }

// ---------------------------------------------------------------------------
// Compile-time Chebyshev fit of f(u) = erf(sqrt(u)/sqrt(2)) / sqrt(u),
// u in [0, 25], degree NC-1 interpolant converted to monomial basis in
// v = u*(2/25) - 1.  All math constexpr (Taylor erf/cos, Newton sqrt).
// Then erf(h/sqrt(2)) ~= h * P(v(h^2)) for |h| <= 5 (clamped).
// ---------------------------------------------------------------------------
namespace fitns {
constexpr double PI_ = 3.14159265358979323846;
constexpr int    NC  = 14;
constexpr double UMAX = 25.0;

constexpr double cerf(double x) {
    double t = x, s = x;
    for (int n = 1; n < 80; n++) {
        t = t * (-(x * x) / n);
        s = s + t / (2.0 * n + 1.0);
    }
    return s * 1.12837916709551257390;      // 2/sqrt(pi)
}
constexpr double ccos(double x) {
    double t = 1.0, s = 1.0;
    for (int n = 1; n < 40; n++) {
        t = t * (-(x * x) / ((2.0 * n - 1.0) * (2.0 * n)));
        s = s + t;
    }
    return s;
}
constexpr double csqrt(double x) {
    double r = (x > 1.0) ? x : 1.0;
    for (int i = 0; i < 100; i++) r = 0.5 * (r + x / r);
    return r;
}
struct Fit { double c[NC]; };
constexpr Fit mkfit() {
    Fit F{};
    double fv[NC] = {}, cth[NC] = {};
    for (int m = 0; m < NC; m++) {
        double th = PI_ * (m + 0.5) / NC;
        double v  = ccos(th);
        cth[m] = v;
        double u = 0.5 * UMAX * (1.0 + v);
        double su = csqrt(u);
        fv[m] = cerf(su * 0.70710678118654752440) / su;
    }
    double a[NC] = {};
    for (int k = 0; k < NC; k++) {
        double s = 0.0;
        for (int m = 0; m < NC; m++) {
            double c0 = 1.0, c1 = cth[m], ck = 1.0;
            if (k == 1) ck = c1;
            else if (k >= 2) {
                for (int i = 2; i <= k; i++) { ck = 2.0 * cth[m] * c1 - c0; c0 = c1; c1 = ck; }
            }
            s += fv[m] * ck;
        }
        a[k] = 2.0 * s / NC;
    }
    a[0] *= 0.5;
    double T0[NC] = {}, T1[NC] = {}, Tn[NC] = {};
    T0[0] = 1.0; T1[1] = 1.0;
    F.c[0] += a[0];
    F.c[1] += a[1];
    for (int k = 2; k < NC; k++) {
        for (int j = 0; j < NC; j++) {
            double tp = (j > 0) ? T1[j - 1] : 0.0;
            Tn[j] = 2.0 * tp - T0[j];
        }
        for (int j = 0; j <= k; j++) F.c[j] += a[k] * Tn[j];
        for (int j = 0; j < NC; j++) { T0[j] = T1[j]; T1[j] = Tn[j]; }
    }
    // fold the 0.5 of gelu = 0.5h + 0.5*|h|*erf(|h|/sqrt2) into the poly
    for (int j = 0; j < NC; j++) F.c[j] *= 0.5;
    return F;
}
constexpr Fit FIT = mkfit();
}  // namespace fitns

__constant__ float d_coef[fitns::NC] = {
    (float)fitns::FIT.c[0],  (float)fitns::FIT.c[1],  (float)fitns::FIT.c[2],
    (float)fitns::FIT.c[3],  (float)fitns::FIT.c[4],  (float)fitns::FIT.c[5],
    (float)fitns::FIT.c[6],  (float)fitns::FIT.c[7],  (float)fitns::FIT.c[8],
    (float)fitns::FIT.c[9],  (float)fitns::FIT.c[10], (float)fitns::FIT.c[11],
    (float)fitns::FIT.c[12], (float)fitns::FIT.c[13]
};

// Scratch for projections (allocation-free: __device__ globals)
__device__ float g_xs[Bsz * Lsz * Hsz];   // xs_proj + b1
__device__ float g_xe[Bsz * Lsz * Hsz];   // xe_proj

// ---------------------------------------------------------------------------
// Kernel 1: fused projection GEMM (f32x2 accumulate).
// ---------------------------------------------------------------------------
#define BM 64
#define BN 64
#define BK 16
#define SPAD 4

__global__ __launch_bounds__(256) void proj_kernel(
    const float* __restrict__ X, const float* __restrict__ W1,
    const float* __restrict__ b1)
{
    __shared__ float As[BK][BM + SPAD];
    __shared__ float Bs[BK][BN + SPAD];

    const int m0  = blockIdx.y * BM;
    const int n0g = blockIdx.x * BN;
    const int half = (n0g >= Hsz) ? 1 : 0;
    const int n0  = n0g - half * Hsz;
    const float* Bbase = W1 + (size_t)half * Hsz * Hsz;
    float* Out = half ? g_xe : g_xs;

    const int tid = threadIdx.x;
    const int tx = tid & 15;
    const int ty = tid >> 4;

    u64 acc2[4][2];
#pragma unroll
    for (int q = 0; q < 4; q++) { acc2[q][0] = bcast2(0.f); acc2[q][1] = bcast2(0.f); }

    const int a_row = tid >> 2;
    const int a_kv  = (tid & 3) * 4;
    const int b_kk = tid >> 4;
    const int b_nv = (tid & 15) * 4;

    for (int k0 = 0; k0 < Hsz; k0 += BK) {
        float4 a = *(const float4*)(X + (size_t)(m0 + a_row) * Hsz + k0 + a_kv);
        As[a_kv + 0][a_row] = a.x;
        As[a_kv + 1][a_row] = a.y;
        As[a_kv + 2][a_row] = a.z;
        As[a_kv + 3][a_row] = a.w;
        float4 bv = *(const float4*)(Bbase + (size_t)(k0 + b_kk) * Hsz + n0 + b_nv);
        *(float4*)&Bs[b_kk][b_nv] = bv;
        __syncthreads();

#pragma unroll
        for (int kk = 0; kk < BK; kk++) {
            float4 av = *(const float4*)&As[kk][ty * 4];
            const ulonglong2* bp = (const ulonglong2*)&Bs[kk][tx * 4];
            ulonglong2 bw = *bp;
            u64 a0 = bcast2(av.x), a1 = bcast2(av.y), a2 = bcast2(av.z), a3 = bcast2(av.w);
            acc2[0][0] = ffma2_(a0, bw.x, acc2[0][0]); acc2[0][1] = ffma2_(a0, bw.y, acc2[0][1]);
            acc2[1][0] = ffma2_(a1, bw.x, acc2[1][0]); acc2[1][1] = ffma2_(a1, bw.y, acc2[1][1]);
            acc2[2][0] = ffma2_(a2, bw.x, acc2[2][0]); acc2[2][1] = ffma2_(a2, bw.y, acc2[2][1]);
            acc2[3][0] = ffma2_(a3, bw.x, acc2[3][0]); acc2[3][1] = ffma2_(a3, bw.y, acc2[3][1]);
        }
        __syncthreads();
    }

#pragma unroll
    for (int q = 0; q < 4; q++) {
        const int row = m0 + ty * 4 + q;
        float v0, v1, v2, v3;
        unpack2(acc2[q][0], v0, v1);
        unpack2(acc2[q][1], v2, v3);
        float vals[4] = {v0, v1, v2, v3};
#pragma unroll
        for (int p = 0; p < 4; p++) {
            const int col = n0 + tx * 4 + p;
            float v = vals[p];
            if (!half) v += b1[col];
            Out[(size_t)row * Hsz + col] = v;
        }
    }
}

// ---------------------------------------------------------------------------
// Kernel 2: fused span scorer, fully f32x2-packed along k.
// ---------------------------------------------------------------------------
#define CK  128
#define CKP 130

__device__ __forceinline__ u64 gelu2(u64 h, const u64* c, u64 s2, u64 m1, u64 hf) {
    u64 ha = habs2_(h);
    u64 hc = fmin2s_(ha, 5.0f);       // clamp |h| <= 5 (2x FMNMX, alu pipe)
    u64 u  = fmul2_(hc, hc);
    u64 v  = ffma2_(u, s2, m1);       // v = u*(2/25) - 1
    u64 p  = c[fitns::NC - 1];
#pragma unroll
    for (int k = fitns::NC - 2; k >= 0; k--) p = ffma2_(p, v, c[k]);
    u64 ea = fmul2_(hc, p);           // 0.5*erf(hc/sqrt2)  (0.5 folded into c)
    u64 th = fmul2_(h, hf);           // 0.5*h
    return ffma2_(ha, ea, th);        // 0.5h + 0.5|h|erf(|h|/sqrt2) = gelu(h)
}

__global__ __launch_bounds__(256) void span_kernel(
    const float* __restrict__ W2, const float* __restrict__ b2,
    float* __restrict__ out)
{
    __shared__ float  xss[16][CKP];
    __shared__ float  xes[16][CKP];
    __shared__ float2 w2c[CK / 2][16];   // [kk2][n] = {W2[2k][n], W2[2k+1][n]}

    const int b  = blockIdx.z;
    const int i0 = blockIdx.y * 16;
    const int j0 = blockIdx.x * 16;
    const int tid = threadIdx.x;
    const int il = tid >> 4;
    const int jl = tid & 15;

    const float* xsrow = g_xs + (size_t)(b * Lsz + i0) * Hsz;
    const float* xerow = g_xe + (size_t)(b * Lsz + j0) * Hsz;

    u64 c[fitns::NC];
#pragma unroll
    for (int k = 0; k < fitns::NC; k++) c[k] = bcast2(d_coef[k]);
    const u64 s2 = bcast2(2.0f / 25.0f);
    const u64 m1 = bcast2(-1.0f);
    const u64 hf = bcast2(0.5f);

    u64 acc[NL];
#pragma unroll
    for (int n = 0; n < NL; n++) acc[n] = bcast2(0.f);

    for (int k0 = 0; k0 < Hsz; k0 += CK) {
        __syncthreads();
        // stage W2 chunk, k-pair packed, n padded to 14->16
#pragma unroll
        for (int e = tid; e < CK * 16; e += 256) {
            int kk = e >> 4, n = e & 15;
            float w = (n < NL) ? W2[(size_t)(k0 + kk) * NL + n] : 0.f;
            ((float*)w2c)[(kk >> 1) * 32 + n * 2 + (kk & 1)] = w;
        }
        // stage xs / xe chunks (k-contiguous rows)
#pragma unroll
        for (int e = tid; e < 16 * (CK / 2); e += 256) {
            int r = e >> 6, cc = e & 63;
            *(float2*)&xss[r][2 * cc] = *(const float2*)(xsrow + (size_t)r * Hsz + k0 + 2 * cc);
            *(float2*)&xes[r][2 * cc] = *(const float2*)(xerow + (size_t)r * Hsz + k0 + 2 * cc);
        }
        __syncthreads();

#pragma unroll 8
        for (int q = 0; q < CK / 2; q++) {
            u64 xs2 = *(const u64*)&xss[il][2 * q];
            u64 xe2 = *(const u64*)&xes[jl][2 * q];
            u64 h = fadd2_(xs2, xe2);
            u64 g = gelu2(h, c, s2, m1, hf);
            const ulonglong2* wr = (const ulonglong2*)&w2c[q][0];
            ulonglong2 w01 = wr[0], w23 = wr[1], w45 = wr[2], w67 = wr[3];
            ulonglong2 w89 = wr[4], wab = wr[5], wcd = wr[6];
            acc[0]  = ffma2_(g, w01.x, acc[0]);
            acc[1]  = ffma2_(g, w01.y, acc[1]);
            acc[2]  = ffma2_(g, w23.x, acc[2]);
            acc[3]  = ffma2_(g, w23.y, acc[3]);
            acc[4]  = ffma2_(g, w45.x, acc[4]);
            acc[5]  = ffma2_(g, w45.y, acc[5]);
            acc[6]  = ffma2_(g, w67.x, acc[6]);
            acc[7]  = ffma2_(g, w67.y, acc[7]);
            acc[8]  = ffma2_(g, w89.x, acc[8]);
            acc[9]  = ffma2_(g, w89.y, acc[9]);
            acc[10] = ffma2_(g, wab.x, acc[10]);
            acc[11] = ffma2_(g, wab.y, acc[11]);
            acc[12] = ffma2_(g, wcd.x, acc[12]);
        }
    }

    float* op = out + ((size_t)(b * Lsz + i0 + il) * Lsz + (j0 + jl)) * NL;
#pragma unroll
    for (int n = 0; n < NL; n++) {
        float lo, hi;
        unpack2(acc[n], lo, hi);
        op[n] = lo + hi + b2[n];
    }
}

// ---------------------------------------------------------------------------
extern "C" void kernel_launch(void* const* d_in, const int* in_sizes, int n_in,
                              void* d_out, int out_size)
{
    const float* X  = (const float*)d_in[0];   // hidden_states (4,256,768)
    const float* W1 = (const float*)d_in[1];   // (1536,768)
    const float* b1 = (const float*)d_in[2];   // (768)
    const float* W2 = (const float*)d_in[3];   // (768,13)
    const float* b2 = (const float*)d_in[4];   // (13)
    float* out = (float*)d_out;                // (4,256,256,13)

    dim3 g1((2 * Hsz) / BN, (Bsz * Lsz) / BM);   // 24 x 16 = 384 blocks
    proj_kernel<<<g1, 256>>>(X, W1, b1);

    dim3 g2(Lsz / 16, Lsz / 16, Bsz);            // 16 x 16 x 4 = 1024 blocks
    span_kernel<<<g2, 256>>>(W2, b2, out);
}

// round 4
// speedup vs baseline: 1.3209x; 1.0921x over previous
#include <cuda_runtime.h>
#include <math.h>

#define Bsz 4
#define Lsz 256
#define Hsz 768
#define NL  13

typedef unsigned long long u64;

// ---------------------------------------------------------------------------
// f32x2 packed helpers (sm_103a: 2x fp32 per issue slot via FFMA2)
// ---------------------------------------------------------------------------
__device__ __forceinline__ u64 pack2(float lo, float hi) {
    u64 r; asm("mov.b64 %0,{%1,%2};" : "=l"(r) : "f"(lo), "f"(hi)); return r;
}
__device__ __forceinline__ u64 bcast2(float x) { return pack2(x, x); }
__device__ __forceinline__ void unpack2(u64 v, float& lo, float& hi) {
    asm("mov.b64 {%0,%1},%2;" : "=f"(lo), "=f"(hi) : "l"(v));
}
__device__ __forceinline__ u64 fadd2_(u64 a, u64 b) {
    u64 d; asm("add.rn.f32x2 %0,%1,%2;" : "=l"(d) : "l"(a), "l"(b)); return d;
}
__device__ __forceinline__ u64 fmul2_(u64 a, u64 b) {
    u64 d; asm("mul.rn.f32x2 %0,%1,%2;" : "=l"(d) : "l"(a), "l"(b)); return d;
}
__device__ __forceinline__ u64 ffma2_(u64 a, u64 b, u64 c) {
    u64 d; asm("fma.rn.f32x2 %0,%1,%2,%3;" : "=l"(d) : "l"(a), "l"(b), "l"(c)); return d;
}
// packed clamp via 2x scalar FMNMX (alu pipe, which has headroom)
__device__ __forceinline__ u64 fmin2s_(u64 a, float b) {
    float lo, hi; unpack2(a, lo, hi);
    return pack2(fminf(lo, b), fminf(hi, b));
}

// ---------------------------------------------------------------------------
// Compile-time Chebyshev fit of S(u) = 0.5*sqrt(u)*erf(sqrt(u/2)), u in
// [0,25], NC coeffs, monomial basis in v = u*(2/25)-1.
// Then gelu(h) = 0.5*h + S(h^2)   (exact identity: h*erf(h/sqrt2) is even).
// ---------------------------------------------------------------------------
namespace fitns {
constexpr double PI_ = 3.14159265358979323846;
constexpr int    NC  = 10;
constexpr double UMAX = 25.0;

constexpr double cerf(double x) {
    double t = x, s = x;
    for (int n = 1; n < 80; n++) {
        t = t * (-(x * x) / n);
        s = s + t / (2.0 * n + 1.0);
    }
    return s * 1.12837916709551257390;      // 2/sqrt(pi)
}
constexpr double ccos(double x) {
    double t = 1.0, s = 1.0;
    for (int n = 1; n < 40; n++) {
        t = t * (-(x * x) / ((2.0 * n - 1.0) * (2.0 * n)));
        s = s + t;
    }
    return s;
}
constexpr double csqrt(double x) {
    double r = (x > 1.0) ? x : 1.0;
    for (int i = 0; i < 100; i++) r = 0.5 * (r + x / r);
    return r;
}
struct Fit { double c[NC]; };
constexpr Fit mkfit() {
    Fit F{};
    double fv[NC] = {}, cth[NC] = {};
    for (int m = 0; m < NC; m++) {
        double th = PI_ * (m + 0.5) / NC;
        double v  = ccos(th);
        cth[m] = v;
        double u = 0.5 * UMAX * (1.0 + v);
        double su = csqrt(u);
        fv[m] = 0.5 * su * cerf(su * 0.70710678118654752440);   // S(u)
    }
    double a[NC] = {};
    for (int k = 0; k < NC; k++) {
        double s = 0.0;
        for (int m = 0; m < NC; m++) {
            double c0 = 1.0, c1 = cth[m], ck = 1.0;
            if (k == 1) ck = c1;
            else if (k >= 2) {
                for (int i = 2; i <= k; i++) { ck = 2.0 * cth[m] * c1 - c0; c0 = c1; c1 = ck; }
            }
            s += fv[m] * ck;
        }
        a[k] = 2.0 * s / NC;
    }
    a[0] *= 0.5;
    double T0[NC] = {}, T1[NC] = {}, Tn[NC] = {};
    T0[0] = 1.0; T1[1] = 1.0;
    F.c[0] += a[0];
    F.c[1] += a[1];
    for (int k = 2; k < NC; k++) {
        for (int j = 0; j < NC; j++) {
            double tp = (j > 0) ? T1[j - 1] : 0.0;
            Tn[j] = 2.0 * tp - T0[j];
        }
        for (int j = 0; j <= k; j++) F.c[j] += a[k] * Tn[j];
        for (int j = 0; j < NC; j++) { T0[j] = T1[j]; T1[j] = Tn[j]; }
    }
    return F;
}
constexpr Fit FIT = mkfit();
}  // namespace fitns

__constant__ float d_coef[fitns::NC] = {
    (float)fitns::FIT.c[0], (float)fitns::FIT.c[1], (float)fitns::FIT.c[2],
    (float)fitns::FIT.c[3], (float)fitns::FIT.c[4], (float)fitns::FIT.c[5],
    (float)fitns::FIT.c[6], (float)fitns::FIT.c[7], (float)fitns::FIT.c[8],
    (float)fitns::FIT.c[9]
};

// Scratch for projections (allocation-free: __device__ globals)
__device__ float g_xs[Bsz * Lsz * Hsz];   // xs_proj + b1
__device__ float g_xe[Bsz * Lsz * Hsz];   // xe_proj

// ---------------------------------------------------------------------------
// Kernel 1: fused projection GEMM (f32x2), double-buffered, 1 sync per step.
// ---------------------------------------------------------------------------
#define BM 64
#define BN 64
#define BK 16
#define SPAD 4

__global__ __launch_bounds__(256) void proj_kernel(
    const float* __restrict__ X, const float* __restrict__ W1,
    const float* __restrict__ b1)
{
    __shared__ float As[2][BK][BM + SPAD];
    __shared__ float Bs[2][BK][BN + SPAD];

    const int m0  = blockIdx.y * BM;
    const int n0g = blockIdx.x * BN;
    const int half = (n0g >= Hsz) ? 1 : 0;
    const int n0  = n0g - half * Hsz;
    const float* Bbase = W1 + (size_t)half * Hsz * Hsz;
    float* Out = half ? g_xe : g_xs;

    const int tid = threadIdx.x;
    const int tx = tid & 15;
    const int ty = tid >> 4;

    u64 acc2[4][2];
#pragma unroll
    for (int q = 0; q < 4; q++) { acc2[q][0] = bcast2(0.f); acc2[q][1] = bcast2(0.f); }

    const int a_row = tid >> 2;
    const int a_kv  = (tid & 3) * 4;
    const int b_kk = tid >> 4;
    const int b_nv = (tid & 15) * 4;

    const float* aptr = X + (size_t)(m0 + a_row) * Hsz + a_kv;
    const float* bptr = Bbase + (size_t)b_kk * Hsz + n0 + b_nv;

    // preload tile 0
    {
        float4 a = *(const float4*)(aptr);
        As[0][a_kv + 0][a_row] = a.x;
        As[0][a_kv + 1][a_row] = a.y;
        As[0][a_kv + 2][a_row] = a.z;
        As[0][a_kv + 3][a_row] = a.w;
        *(float4*)&Bs[0][b_kk][b_nv] = *(const float4*)(bptr);
    }

    const int NT = Hsz / BK;   // 48
    for (int kt = 0; kt < NT; kt++) {
        __syncthreads();
        const int cur = kt & 1;
        float4 an, bn;
        const bool more = (kt + 1 < NT);
        if (more) {
            an = *(const float4*)(aptr + (kt + 1) * BK);
            bn = *(const float4*)(bptr + (size_t)(kt + 1) * BK * Hsz);
        }
#pragma unroll
        for (int kk = 0; kk < BK; kk++) {
            float4 av = *(const float4*)&As[cur][kk][ty * 4];
            ulonglong2 bw = *(const ulonglong2*)&Bs[cur][kk][tx * 4];
            u64 a0 = bcast2(av.x), a1 = bcast2(av.y), a2 = bcast2(av.z), a3 = bcast2(av.w);
            acc2[0][0] = ffma2_(a0, bw.x, acc2[0][0]); acc2[0][1] = ffma2_(a0, bw.y, acc2[0][1]);
            acc2[1][0] = ffma2_(a1, bw.x, acc2[1][0]); acc2[1][1] = ffma2_(a1, bw.y, acc2[1][1]);
            acc2[2][0] = ffma2_(a2, bw.x, acc2[2][0]); acc2[2][1] = ffma2_(a2, bw.y, acc2[2][1]);
            acc2[3][0] = ffma2_(a3, bw.x, acc2[3][0]); acc2[3][1] = ffma2_(a3, bw.y, acc2[3][1]);
        }
        if (more) {
            const int nxt = cur ^ 1;
            As[nxt][a_kv + 0][a_row] = an.x;
            As[nxt][a_kv + 1][a_row] = an.y;
            As[nxt][a_kv + 2][a_row] = an.z;
            As[nxt][a_kv + 3][a_row] = an.w;
            *(float4*)&Bs[nxt][b_kk][b_nv] = bn;
        }
    }

#pragma unroll
    for (int q = 0; q < 4; q++) {
        const int row = m0 + ty * 4 + q;
        float v0, v1, v2, v3;
        unpack2(acc2[q][0], v0, v1);
        unpack2(acc2[q][1], v2, v3);
        float vals[4] = {v0, v1, v2, v3};
#pragma unroll
        for (int p = 0; p < 4; p++) {
            const int col = n0 + tx * 4 + p;
            float v = vals[p];
            if (!half) v += b1[col];
            Out[(size_t)row * Hsz + col] = v;
        }
    }
}

// ---------------------------------------------------------------------------
// Kernel 2: fused span scorer, f32x2-packed along k.
//   gelu(h) = 0.5h + S(h^2), S = degree-(NC-1) poly in v = u*(2/25)-1.
// ---------------------------------------------------------------------------
#define CK  128
#define CKP 130

__device__ __forceinline__ u64 gelu2(u64 h, const u64* c, u64 s2, u64 m1, u64 hf) {
    u64 u = fmul2_(h, h);
    u = fmin2s_(u, 25.0f);            // safety clamp (alu pipe)
    u64 v = ffma2_(u, s2, m1);
    u64 p = c[fitns::NC - 1];
#pragma unroll
    for (int k = fitns::NC - 2; k >= 0; k--) p = ffma2_(p, v, c[k]);
    return ffma2_(h, hf, p);          // 0.5h + S(h^2)
}

__global__ __launch_bounds__(256) void span_kernel(
    const float* __restrict__ W2, const float* __restrict__ b2,
    float* __restrict__ out)
{
    __shared__ float  xss[16][CKP];
    __shared__ float  xes[16][CKP];
    __shared__ float2 w2c[CK / 2][16];   // [kk2][n] = {W2[2k][n], W2[2k+1][n]}

    const int b  = blockIdx.z;
    const int i0 = blockIdx.y * 16;
    const int j0 = blockIdx.x * 16;
    const int tid = threadIdx.x;
    const int il = tid >> 4;
    const int jl = tid & 15;

    const float* xsrow = g_xs + (size_t)(b * Lsz + i0) * Hsz;
    const float* xerow = g_xe + (size_t)(b * Lsz + j0) * Hsz;

    u64 c[fitns::NC];
#pragma unroll
    for (int k = 0; k < fitns::NC; k++) c[k] = bcast2(d_coef[k]);
    const u64 s2 = bcast2(2.0f / 25.0f);
    const u64 m1 = bcast2(-1.0f);
    const u64 hf = bcast2(0.5f);

    u64 acc[NL];
#pragma unroll
    for (int n = 0; n < NL; n++) acc[n] = bcast2(0.f);

    for (int k0 = 0; k0 < Hsz; k0 += CK) {
        __syncthreads();
        // stage W2 chunk, k-pair packed, n padded to 14->16
#pragma unroll
        for (int e = tid; e < CK * 16; e += 256) {
            int kk = e >> 4, n = e & 15;
            float w = (n < NL) ? W2[(size_t)(k0 + kk) * NL + n] : 0.f;
            ((float*)w2c)[(kk >> 1) * 32 + n * 2 + (kk & 1)] = w;
        }
        // stage xs / xe chunks (k-contiguous rows)
#pragma unroll
        for (int e = tid; e < 16 * (CK / 2); e += 256) {
            int r = e >> 6, cc = e & 63;
            *(float2*)&xss[r][2 * cc] = *(const float2*)(xsrow + (size_t)r * Hsz + k0 + 2 * cc);
            *(float2*)&xes[r][2 * cc] = *(const float2*)(xerow + (size_t)r * Hsz + k0 + 2 * cc);
        }
        __syncthreads();

#pragma unroll 8
        for (int q = 0; q < CK / 2; q++) {
            u64 xs2 = *(const u64*)&xss[il][2 * q];
            u64 xe2 = *(const u64*)&xes[jl][2 * q];
            u64 h = fadd2_(xs2, xe2);
            u64 g = gelu2(h, c, s2, m1, hf);
            const ulonglong2* wr = (const ulonglong2*)&w2c[q][0];
            ulonglong2 w01 = wr[0], w23 = wr[1], w45 = wr[2], w67 = wr[3];
            ulonglong2 w89 = wr[4], wab = wr[5], wcd = wr[6];
            acc[0]  = ffma2_(g, w01.x, acc[0]);
            acc[1]  = ffma2_(g, w01.y, acc[1]);
            acc[2]  = ffma2_(g, w23.x, acc[2]);
            acc[3]  = ffma2_(g, w23.y, acc[3]);
            acc[4]  = ffma2_(g, w45.x, acc[4]);
            acc[5]  = ffma2_(g, w45.y, acc[5]);
            acc[6]  = ffma2_(g, w67.x, acc[6]);
            acc[7]  = ffma2_(g, w67.y, acc[7]);
            acc[8]  = ffma2_(g, w89.x, acc[8]);
            acc[9]  = ffma2_(g, w89.y, acc[9]);
            acc[10] = ffma2_(g, wab.x, acc[10]);
            acc[11] = ffma2_(g, wab.y, acc[11]);
            acc[12] = ffma2_(g, wcd.x, acc[12]);
        }
    }

    float* op = out + ((size_t)(b * Lsz + i0 + il) * Lsz + (j0 + jl)) * NL;
#pragma unroll
    for (int n = 0; n < NL; n++) {
        float lo, hi;
        unpack2(acc[n], lo, hi);
        op[n] = lo + hi + b2[n];
    }
}

// ---------------------------------------------------------------------------
extern "C" void kernel_launch(void* const* d_in, const int* in_sizes, int n_in,
                              void* d_out, int out_size)
{
    const float* X  = (const float*)d_in[0];   // hidden_states (4,256,768)
    const float* W1 = (const float*)d_in[1];   // (1536,768)
    const float* b1 = (const float*)d_in[2];   // (768)
    const float* W2 = (const float*)d_in[3];   // (768,13)
    const float* b2 = (const float*)d_in[4];   // (13)
    float* out = (float*)d_out;                // (4,256,256,13)

    dim3 g1((2 * Hsz) / BN, (Bsz * Lsz) / BM);   // 24 x 16 = 384 blocks
    proj_kernel<<<g1, 256>>>(X, W1, b1);

    dim3 g2(Lsz / 16, Lsz / 16, Bsz);            // 16 x 16 x 4 = 1024 blocks
    span_kernel<<<g2, 256>>>(W2, b2, out);
}